// round 1
// baseline (speedup 1.0000x reference)
#include <cuda_runtime.h>
#include <math.h>

#define BATCH 4
#define SEQ   4096
#define CDIM  128
#define MTOT  (BATCH*SEQ)   // 16384

// Scratch for Q,K,V projections (8 MB each) — __device__ globals per harness rules.
__device__ float g_Q[MTOT*CDIM];
__device__ float g_K[MTOT*CDIM];
__device__ float g_V[MTOT*CDIM];

// XOR swizzle for 64x128-float tiles stored as float4 (32 f4 per row):
// conflict-free for both row-contiguous loads and 4-row-strided per-thread reads.
__device__ __forceinline__ int sw_idx(int row, int kc) {
    return row * 32 + (kc ^ (row & 31));
}

// ---------------------------------------------------------------------------
// Kernel 1: QKV projection. out[m][c] = sum_k x[m][k]*W_fc[k][c] + b_fc[c]
// Grid: (256 m-tiles, 6 c-tiles of 64). Block: 256 threads, 4x4 micro-tiles.
// ---------------------------------------------------------------------------
__global__ __launch_bounds__(256, 1)
void qkv_kernel(const float* __restrict__ x, const float* __restrict__ Wfc,
                const float* __restrict__ bfc) {
    extern __shared__ float smem[];
    float4* Xs4 = (float4*)smem;               // 64x128 swizzled (2048 f4)
    float4* Ws4 = (float4*)(smem + 8192);      // 128 rows x 68 floats (17 f4 stride)

    const int tid = threadIdx.x;
    const int tx = tid & 15, ty = tid >> 4;
    const int m0 = ty * 4, n0 = tx * 4;
    const int mbase = blockIdx.x * 64;
    const int cbase = blockIdx.y * 64;

    // Load X tile (64 rows x 128 floats, contiguous)
    const float4* xg = (const float4*)(x + (size_t)mbase * CDIM);
    #pragma unroll
    for (int i = 0; i < 8; i++) {
        int idx = i * 256 + tid;           // 0..2047
        Xs4[sw_idx(idx >> 5, idx & 31)] = xg[idx];
    }
    // Load W tile [128][64] with stride-68 padding (conflict-free)
    #pragma unroll
    for (int i = 0; i < 8; i++) {
        int idx = i * 256 + tid;           // 0..2047
        int kr = idx >> 4, nq = idx & 15;
        Ws4[kr * 17 + nq] = ((const float4*)(Wfc + kr * 384 + cbase))[nq];
    }
    __syncthreads();

    float acc[4][4];
    #pragma unroll
    for (int i = 0; i < 4; i++)
        #pragma unroll
        for (int j = 0; j < 4; j++) acc[i][j] = 0.f;

    #pragma unroll 4
    for (int k4 = 0; k4 < 32; k4++) {
        float4 b0 = Ws4[(4 * k4 + 0) * 17 + tx];
        float4 b1 = Ws4[(4 * k4 + 1) * 17 + tx];
        float4 b2 = Ws4[(4 * k4 + 2) * 17 + tx];
        float4 b3 = Ws4[(4 * k4 + 3) * 17 + tx];
        #pragma unroll
        for (int i = 0; i < 4; i++) {
            float4 a = Xs4[sw_idx(m0 + i, k4)];
            acc[i][0] += a.x * b0.x + a.y * b1.x + a.z * b2.x + a.w * b3.x;
            acc[i][1] += a.x * b0.y + a.y * b1.y + a.z * b2.y + a.w * b3.y;
            acc[i][2] += a.x * b0.z + a.y * b1.z + a.z * b2.z + a.w * b3.z;
            acc[i][3] += a.x * b0.w + a.y * b1.w + a.z * b2.w + a.w * b3.w;
        }
    }

    float4 bias = *(const float4*)(bfc + cbase + n0);
    int sel = cbase >> 7;                       // 0->Q, 1->K, 2->V
    float* buf = (sel == 0) ? g_Q : (sel == 1) ? g_K : g_V;
    int lc = (cbase & 127) + n0;
    #pragma unroll
    for (int i = 0; i < 4; i++) {
        float4 o;
        o.x = acc[i][0] + bias.x;
        o.y = acc[i][1] + bias.y;
        o.z = acc[i][2] + bias.z;
        o.w = acc[i][3] + bias.w;
        *(float4*)(buf + (size_t)(mbase + m0 + i) * CDIM + lc) = o;
    }
}

// ---------------------------------------------------------------------------
// Kernel 2: flash attention + fused output projection.
// Grid: (64 q-tiles, 4 batches). Block: 256 threads.
// Per CTA: 64-row Q tile; loop over 64 KV tiles of 64 rows; online softmax.
// Then out = (O/l) @ W_out + b_out with W_out cached in SMEM (reuses K/V space).
// ---------------------------------------------------------------------------
__global__ __launch_bounds__(256, 1)
void attn_kernel(const float* __restrict__ Wout, const float* __restrict__ bout,
                 const float* __restrict__ scale, float* __restrict__ out) {
    extern __shared__ float smem[];
    float4* Qs4 = (float4*)smem;                 // 2048 f4, swizzled
    float4* Ks4 = (float4*)(smem + 8192);        // 2048 f4, swizzled
    float4* Vs4 = (float4*)(smem + 16384);       // 2048 f4, linear
    float*  Psm = smem + 24576;                  // 64 x 68 floats (padded)
    float4* Ws4 = (float4*)(smem + 8192);        // reuse K+V region: 4096 f4 (64 KB)
    float*  OsmF = smem;                         // reuse Q region for O

    const int tid = threadIdx.x;
    const int tx = tid & 15, ty = tid >> 4;
    const int m0 = ty * 4, n0 = tx * 4, c0 = tx * 8;
    const int b = blockIdx.y;
    const int qr0 = blockIdx.x * 64;

    const float s0 = scale[0];
    const float sc = 1.0f / (sqrtf((float)CDIM) * s0);

    // Load Q tile
    const float4* qg = (const float4*)(g_Q + (size_t)(b * SEQ + qr0) * CDIM);
    #pragma unroll
    for (int i = 0; i < 8; i++) {
        int idx = i * 256 + tid;
        Qs4[sw_idx(idx >> 5, idx & 31)] = qg[idx];
    }

    float O[4][8];
    float mrow[4], lrow[4];
    #pragma unroll
    for (int i = 0; i < 4; i++) {
        mrow[i] = -1e30f; lrow[i] = 0.f;
        #pragma unroll
        for (int cc = 0; cc < 8; cc++) O[i][cc] = 0.f;
    }

    for (int jt = 0; jt < SEQ / 64; jt++) {
        __syncthreads();   // prior iter's P/V reads complete (and Q visible after next sync)
        const int kr0 = jt * 64;
        const float4* kg = (const float4*)(g_K + (size_t)(b * SEQ + kr0) * CDIM);
        const float4* vg = (const float4*)(g_V + (size_t)(b * SEQ + kr0) * CDIM);
        #pragma unroll
        for (int i = 0; i < 8; i++) {
            int idx = i * 256 + tid;
            Ks4[sw_idx(idx >> 5, idx & 31)] = kg[idx];
            Vs4[idx] = vg[idx];
        }
        __syncthreads();

        // S = (Q . K) over k=128
        float s[4][4];
        #pragma unroll
        for (int i = 0; i < 4; i++)
            #pragma unroll
            for (int j = 0; j < 4; j++) s[i][j] = 0.f;

        #pragma unroll 4
        for (int k4 = 0; k4 < 32; k4++) {
            float4 b0 = Ks4[sw_idx(n0 + 0, k4)];
            float4 b1 = Ks4[sw_idx(n0 + 1, k4)];
            float4 b2 = Ks4[sw_idx(n0 + 2, k4)];
            float4 b3 = Ks4[sw_idx(n0 + 3, k4)];
            #pragma unroll
            for (int i = 0; i < 4; i++) {
                float4 a = Qs4[sw_idx(m0 + i, k4)];
                s[i][0] += a.x * b0.x + a.y * b0.y + a.z * b0.z + a.w * b0.w;
                s[i][1] += a.x * b1.x + a.y * b1.y + a.z * b1.z + a.w * b1.w;
                s[i][2] += a.x * b2.x + a.y * b2.y + a.z * b2.z + a.w * b2.w;
                s[i][3] += a.x * b3.x + a.y * b3.y + a.z * b3.z + a.w * b3.w;
            }
        }

        // Online softmax (row reductions across the 16 tx lanes of each ty group;
        // lanes [0..15]/[16..31] of a warp hold ty even/odd -> xor<=8 stays in group)
        #pragma unroll
        for (int i = 0; i < 4; i++) {
            s[i][0] *= sc; s[i][1] *= sc; s[i][2] *= sc; s[i][3] *= sc;
            float rm = fmaxf(fmaxf(s[i][0], s[i][1]), fmaxf(s[i][2], s[i][3]));
            rm = fmaxf(rm, __shfl_xor_sync(0xffffffffu, rm, 1));
            rm = fmaxf(rm, __shfl_xor_sync(0xffffffffu, rm, 2));
            rm = fmaxf(rm, __shfl_xor_sync(0xffffffffu, rm, 4));
            rm = fmaxf(rm, __shfl_xor_sync(0xffffffffu, rm, 8));
            float nm = fmaxf(mrow[i], rm);
            float al = __expf(mrow[i] - nm);
            mrow[i] = nm;
            float rs = 0.f;
            #pragma unroll
            for (int j = 0; j < 4; j++) {
                float p = __expf(s[i][j] - nm);
                s[i][j] = p; rs += p;
            }
            rs += __shfl_xor_sync(0xffffffffu, rs, 1);
            rs += __shfl_xor_sync(0xffffffffu, rs, 2);
            rs += __shfl_xor_sync(0xffffffffu, rs, 4);
            rs += __shfl_xor_sync(0xffffffffu, rs, 8);
            lrow[i] = lrow[i] * al + rs;
            #pragma unroll
            for (int cc = 0; cc < 8; cc++) O[i][cc] *= al;
        }

        // Stage P in SMEM (stride 68 -> conflict-free STS.128)
        #pragma unroll
        for (int i = 0; i < 4; i++)
            *(float4*)&Psm[(m0 + i) * 68 + n0] =
                make_float4(s[i][0], s[i][1], s[i][2], s[i][3]);
        __syncthreads();

        // O += P @ V
        #pragma unroll 4
        for (int kk = 0; kk < 64; kk++) {
            float4 v0 = Vs4[kk * 32 + 2 * tx];
            float4 v1 = Vs4[kk * 32 + 2 * tx + 1];
            #pragma unroll
            for (int i = 0; i < 4; i++) {
                float p = Psm[(m0 + i) * 68 + kk];
                O[i][0] += p * v0.x; O[i][1] += p * v0.y;
                O[i][2] += p * v0.z; O[i][3] += p * v0.w;
                O[i][4] += p * v1.x; O[i][5] += p * v1.y;
                O[i][6] += p * v1.z; O[i][7] += p * v1.w;
            }
        }
    }
    __syncthreads();

    // Normalize, stash O into SMEM (Q region), cache W_out into K+V region
    #pragma unroll
    for (int i = 0; i < 4; i++) {
        float inv = 1.0f / lrow[i];
        Qs4[sw_idx(m0 + i, 2 * tx)] =
            make_float4(O[i][0] * inv, O[i][1] * inv, O[i][2] * inv, O[i][3] * inv);
        Qs4[sw_idx(m0 + i, 2 * tx + 1)] =
            make_float4(O[i][4] * inv, O[i][5] * inv, O[i][6] * inv, O[i][7] * inv);
    }
    #pragma unroll
    for (int i = 0; i < 16; i++) {
        int idx = i * 256 + tid;           // 0..4095 f4 = full 128x128 W_out
        Ws4[idx] = ((const float4*)Wout)[idx];
    }
    __syncthreads();

    // out = O @ W_out + b_out (fused)
    float acc2[4][8];
    #pragma unroll
    for (int i = 0; i < 4; i++)
        #pragma unroll
        for (int cc = 0; cc < 8; cc++) acc2[i][cc] = 0.f;

    #pragma unroll 4
    for (int k = 0; k < 128; k++) {
        float4 w0 = Ws4[k * 32 + 2 * tx];
        float4 w1 = Ws4[k * 32 + 2 * tx + 1];
        #pragma unroll
        for (int i = 0; i < 4; i++) {
            float a = OsmF[sw_idx(m0 + i, k >> 2) * 4 + (k & 3)];
            acc2[i][0] += a * w0.x; acc2[i][1] += a * w0.y;
            acc2[i][2] += a * w0.z; acc2[i][3] += a * w0.w;
            acc2[i][4] += a * w1.x; acc2[i][5] += a * w1.y;
            acc2[i][6] += a * w1.z; acc2[i][7] += a * w1.w;
        }
    }

    float4 bo0 = ((const float4*)bout)[2 * tx];
    float4 bo1 = ((const float4*)bout)[2 * tx + 1];
    #pragma unroll
    for (int i = 0; i < 4; i++) {
        float4 r0 = make_float4(acc2[i][0] + bo0.x, acc2[i][1] + bo0.y,
                                acc2[i][2] + bo0.z, acc2[i][3] + bo0.w);
        float4 r1 = make_float4(acc2[i][4] + bo1.x, acc2[i][5] + bo1.y,
                                acc2[i][6] + bo1.z, acc2[i][7] + bo1.w);
        float* dst = out + (size_t)(b * SEQ + qr0 + m0 + i) * CDIM + c0;
        *(float4*)dst = r0;
        *(float4*)(dst + 4) = r1;
    }
}

// ---------------------------------------------------------------------------
extern "C" void kernel_launch(void* const* d_in, const int* in_sizes, int n_in,
                              void* d_out, int out_size) {
    const float* x    = (const float*)d_in[0];   // [4,4096,128]
    const float* Wfc  = (const float*)d_in[1];   // [128,384]
    const float* bfc  = (const float*)d_in[2];   // [384]
    const float* Wout = (const float*)d_in[3];   // [128,128]
    const float* bo   = (const float*)d_in[4];   // [128]
    const float* sc   = (const float*)d_in[5];   // [1]
    float* out = (float*)d_out;                  // [4,4096,128]

    const int smem1 = (8192 + 128 * 68) * 4;          // 67584 B
    const int smem2 = (8192 * 3 + 64 * 68) * 4;       // 115712 B
    cudaFuncSetAttribute(qkv_kernel, cudaFuncAttributeMaxDynamicSharedMemorySize, smem1);
    cudaFuncSetAttribute(attn_kernel, cudaFuncAttributeMaxDynamicSharedMemorySize, smem2);

    qkv_kernel<<<dim3(256, 6), 256, smem1>>>(x, Wfc, bfc);
    attn_kernel<<<dim3(64, 4), 256, smem2>>>(Wout, bo, sc, out);
}

// round 2
// speedup vs baseline: 1.0004x; 1.0004x over previous
#include <cuda_runtime.h>
#include <math.h>

#define BATCH 4
#define SEQ   4096
#define CDIM  128
#define MTOT  (BATCH*SEQ)   // 16384

// Scratch for Q,K,V projections (8 MB each) — __device__ globals per harness rules.
__device__ float g_Q[MTOT*CDIM];
__device__ float g_K[MTOT*CDIM];
__device__ float g_V[MTOT*CDIM];

// XOR swizzle for 64x128-float tiles stored as float4 (32 f4 per row):
// conflict-free for both row-contiguous loads and 4-row-strided per-thread reads.
__device__ __forceinline__ int sw_idx(int row, int kc) {
    return row * 32 + (kc ^ (row & 31));
}

// ---------------------------------------------------------------------------
// Kernel 1: QKV projection. out[m][c] = sum_k x[m][k]*W_fc[k][c] + b_fc[c]
// Grid: (256 m-tiles, 6 c-tiles of 64). Block: 256 threads, 4x4 micro-tiles.
// ---------------------------------------------------------------------------
__global__ __launch_bounds__(256, 1)
void qkv_kernel(const float* __restrict__ x, const float* __restrict__ Wfc,
                const float* __restrict__ bfc) {
    extern __shared__ float smem[];
    float4* Xs4 = (float4*)smem;               // 64x128 swizzled (2048 f4)
    float4* Ws4 = (float4*)(smem + 8192);      // 128 rows x 68 floats (17 f4 stride)

    const int tid = threadIdx.x;
    const int tx = tid & 15, ty = tid >> 4;
    const int m0 = ty * 4, n0 = tx * 4;
    const int mbase = blockIdx.x * 64;
    const int cbase = blockIdx.y * 64;

    // Load X tile (64 rows x 128 floats, contiguous)
    const float4* xg = (const float4*)(x + (size_t)mbase * CDIM);
    #pragma unroll
    for (int i = 0; i < 8; i++) {
        int idx = i * 256 + tid;           // 0..2047
        Xs4[sw_idx(idx >> 5, idx & 31)] = xg[idx];
    }
    // Load W tile [128][64] with stride-68 padding (conflict-free)
    #pragma unroll
    for (int i = 0; i < 8; i++) {
        int idx = i * 256 + tid;           // 0..2047
        int kr = idx >> 4, nq = idx & 15;
        Ws4[kr * 17 + nq] = ((const float4*)(Wfc + kr * 384 + cbase))[nq];
    }
    __syncthreads();

    float acc[4][4];
    #pragma unroll
    for (int i = 0; i < 4; i++)
        #pragma unroll
        for (int j = 0; j < 4; j++) acc[i][j] = 0.f;

    #pragma unroll 4
    for (int k4 = 0; k4 < 32; k4++) {
        float4 b0 = Ws4[(4 * k4 + 0) * 17 + tx];
        float4 b1 = Ws4[(4 * k4 + 1) * 17 + tx];
        float4 b2 = Ws4[(4 * k4 + 2) * 17 + tx];
        float4 b3 = Ws4[(4 * k4 + 3) * 17 + tx];
        #pragma unroll
        for (int i = 0; i < 4; i++) {
            float4 a = Xs4[sw_idx(m0 + i, k4)];
            acc[i][0] += a.x * b0.x + a.y * b1.x + a.z * b2.x + a.w * b3.x;
            acc[i][1] += a.x * b0.y + a.y * b1.y + a.z * b2.y + a.w * b3.y;
            acc[i][2] += a.x * b0.z + a.y * b1.z + a.z * b2.z + a.w * b3.z;
            acc[i][3] += a.x * b0.w + a.y * b1.w + a.z * b2.w + a.w * b3.w;
        }
    }

    float4 bias = *(const float4*)(bfc + cbase + n0);
    int sel = cbase >> 7;                       // 0->Q, 1->K, 2->V
    float* buf = (sel == 0) ? g_Q : (sel == 1) ? g_K : g_V;
    int lc = (cbase & 127) + n0;
    #pragma unroll
    for (int i = 0; i < 4; i++) {
        float4 o;
        o.x = acc[i][0] + bias.x;
        o.y = acc[i][1] + bias.y;
        o.z = acc[i][2] + bias.z;
        o.w = acc[i][3] + bias.w;
        *(float4*)(buf + (size_t)(mbase + m0 + i) * CDIM + lc) = o;
    }
}

// ---------------------------------------------------------------------------
// Kernel 2: flash attention + fused output projection.
// Grid: (64 q-tiles, 4 batches). Block: 256 threads.
// Per CTA: 64-row Q tile; loop over 64 KV tiles of 64 rows; online softmax.
// Then out = (O/l) @ W_out + b_out with W_out cached in SMEM (reuses K/V space).
// ---------------------------------------------------------------------------
__global__ __launch_bounds__(256, 1)
void attn_kernel(const float* __restrict__ Wout, const float* __restrict__ bout,
                 const float* __restrict__ scale, float* __restrict__ out) {
    extern __shared__ float smem[];
    float4* Qs4 = (float4*)smem;                 // 2048 f4, swizzled
    float4* Ks4 = (float4*)(smem + 8192);        // 2048 f4, swizzled
    float4* Vs4 = (float4*)(smem + 16384);       // 2048 f4, linear
    float*  Psm = smem + 24576;                  // 64 x 68 floats (padded)
    float4* Ws4 = (float4*)(smem + 8192);        // reuse K+V region: 4096 f4 (64 KB)
    float*  OsmF = smem;                         // reuse Q region for O

    const int tid = threadIdx.x;
    const int tx = tid & 15, ty = tid >> 4;
    const int m0 = ty * 4, n0 = tx * 4, c0 = tx * 8;
    const int b = blockIdx.y;
    const int qr0 = blockIdx.x * 64;

    const float s0 = scale[0];
    const float sc = 1.0f / (sqrtf((float)CDIM) * s0);

    // Load Q tile
    const float4* qg = (const float4*)(g_Q + (size_t)(b * SEQ + qr0) * CDIM);
    #pragma unroll
    for (int i = 0; i < 8; i++) {
        int idx = i * 256 + tid;
        Qs4[sw_idx(idx >> 5, idx & 31)] = qg[idx];
    }

    float O[4][8];
    float mrow[4], lrow[4];
    #pragma unroll
    for (int i = 0; i < 4; i++) {
        mrow[i] = -1e30f; lrow[i] = 0.f;
        #pragma unroll
        for (int cc = 0; cc < 8; cc++) O[i][cc] = 0.f;
    }

    for (int jt = 0; jt < SEQ / 64; jt++) {
        __syncthreads();   // prior iter's P/V reads complete (and Q visible after next sync)
        const int kr0 = jt * 64;
        const float4* kg = (const float4*)(g_K + (size_t)(b * SEQ + kr0) * CDIM);
        const float4* vg = (const float4*)(g_V + (size_t)(b * SEQ + kr0) * CDIM);
        #pragma unroll
        for (int i = 0; i < 8; i++) {
            int idx = i * 256 + tid;
            Ks4[sw_idx(idx >> 5, idx & 31)] = kg[idx];
            Vs4[idx] = vg[idx];
        }
        __syncthreads();

        // S = (Q . K) over k=128
        float s[4][4];
        #pragma unroll
        for (int i = 0; i < 4; i++)
            #pragma unroll
            for (int j = 0; j < 4; j++) s[i][j] = 0.f;

        #pragma unroll 4
        for (int k4 = 0; k4 < 32; k4++) {
            float4 b0 = Ks4[sw_idx(n0 + 0, k4)];
            float4 b1 = Ks4[sw_idx(n0 + 1, k4)];
            float4 b2 = Ks4[sw_idx(n0 + 2, k4)];
            float4 b3 = Ks4[sw_idx(n0 + 3, k4)];
            #pragma unroll
            for (int i = 0; i < 4; i++) {
                float4 a = Qs4[sw_idx(m0 + i, k4)];
                s[i][0] += a.x * b0.x + a.y * b0.y + a.z * b0.z + a.w * b0.w;
                s[i][1] += a.x * b1.x + a.y * b1.y + a.z * b1.z + a.w * b1.w;
                s[i][2] += a.x * b2.x + a.y * b2.y + a.z * b2.z + a.w * b2.w;
                s[i][3] += a.x * b3.x + a.y * b3.y + a.z * b3.z + a.w * b3.w;
            }
        }

        // Online softmax (row reductions across the 16 tx lanes of each ty group;
        // lanes [0..15]/[16..31] of a warp hold ty even/odd -> xor<=8 stays in group)
        #pragma unroll
        for (int i = 0; i < 4; i++) {
            s[i][0] *= sc; s[i][1] *= sc; s[i][2] *= sc; s[i][3] *= sc;
            float rm = fmaxf(fmaxf(s[i][0], s[i][1]), fmaxf(s[i][2], s[i][3]));
            rm = fmaxf(rm, __shfl_xor_sync(0xffffffffu, rm, 1));
            rm = fmaxf(rm, __shfl_xor_sync(0xffffffffu, rm, 2));
            rm = fmaxf(rm, __shfl_xor_sync(0xffffffffu, rm, 4));
            rm = fmaxf(rm, __shfl_xor_sync(0xffffffffu, rm, 8));
            float nm = fmaxf(mrow[i], rm);
            float al = __expf(mrow[i] - nm);
            mrow[i] = nm;
            float rs = 0.f;
            #pragma unroll
            for (int j = 0; j < 4; j++) {
                float p = __expf(s[i][j] - nm);
                s[i][j] = p; rs += p;
            }
            rs += __shfl_xor_sync(0xffffffffu, rs, 1);
            rs += __shfl_xor_sync(0xffffffffu, rs, 2);
            rs += __shfl_xor_sync(0xffffffffu, rs, 4);
            rs += __shfl_xor_sync(0xffffffffu, rs, 8);
            lrow[i] = lrow[i] * al + rs;
            #pragma unroll
            for (int cc = 0; cc < 8; cc++) O[i][cc] *= al;
        }

        // Stage P in SMEM (stride 68 -> conflict-free STS.128)
        #pragma unroll
        for (int i = 0; i < 4; i++)
            *(float4*)&Psm[(m0 + i) * 68 + n0] =
                make_float4(s[i][0], s[i][1], s[i][2], s[i][3]);
        __syncthreads();

        // O += P @ V
        #pragma unroll 4
        for (int kk = 0; kk < 64; kk++) {
            float4 v0 = Vs4[kk * 32 + 2 * tx];
            float4 v1 = Vs4[kk * 32 + 2 * tx + 1];
            #pragma unroll
            for (int i = 0; i < 4; i++) {
                float p = Psm[(m0 + i) * 68 + kk];
                O[i][0] += p * v0.x; O[i][1] += p * v0.y;
                O[i][2] += p * v0.z; O[i][3] += p * v0.w;
                O[i][4] += p * v1.x; O[i][5] += p * v1.y;
                O[i][6] += p * v1.z; O[i][7] += p * v1.w;
            }
        }
    }
    __syncthreads();

    // Normalize, stash O into SMEM (Q region), cache W_out into K+V region
    #pragma unroll
    for (int i = 0; i < 4; i++) {
        float inv = 1.0f / lrow[i];
        Qs4[sw_idx(m0 + i, 2 * tx)] =
            make_float4(O[i][0] * inv, O[i][1] * inv, O[i][2] * inv, O[i][3] * inv);
        Qs4[sw_idx(m0 + i, 2 * tx + 1)] =
            make_float4(O[i][4] * inv, O[i][5] * inv, O[i][6] * inv, O[i][7] * inv);
    }
    #pragma unroll
    for (int i = 0; i < 16; i++) {
        int idx = i * 256 + tid;           // 0..4095 f4 = full 128x128 W_out
        Ws4[idx] = ((const float4*)Wout)[idx];
    }
    __syncthreads();

    // out = O @ W_out + b_out (fused)
    float acc2[4][8];
    #pragma unroll
    for (int i = 0; i < 4; i++)
        #pragma unroll
        for (int cc = 0; cc < 8; cc++) acc2[i][cc] = 0.f;

    #pragma unroll 4
    for (int k = 0; k < 128; k++) {
        float4 w0 = Ws4[k * 32 + 2 * tx];
        float4 w1 = Ws4[k * 32 + 2 * tx + 1];
        #pragma unroll
        for (int i = 0; i < 4; i++) {
            float a = OsmF[sw_idx(m0 + i, k >> 2) * 4 + (k & 3)];
            acc2[i][0] += a * w0.x; acc2[i][1] += a * w0.y;
            acc2[i][2] += a * w0.z; acc2[i][3] += a * w0.w;
            acc2[i][4] += a * w1.x; acc2[i][5] += a * w1.y;
            acc2[i][6] += a * w1.z; acc2[i][7] += a * w1.w;
        }
    }

    float4 bo0 = ((const float4*)bout)[2 * tx];
    float4 bo1 = ((const float4*)bout)[2 * tx + 1];
    #pragma unroll
    for (int i = 0; i < 4; i++) {
        float4 r0 = make_float4(acc2[i][0] + bo0.x, acc2[i][1] + bo0.y,
                                acc2[i][2] + bo0.z, acc2[i][3] + bo0.w);
        float4 r1 = make_float4(acc2[i][4] + bo1.x, acc2[i][5] + bo1.y,
                                acc2[i][6] + bo1.z, acc2[i][7] + bo1.w);
        float* dst = out + (size_t)(b * SEQ + qr0 + m0 + i) * CDIM + c0;
        *(float4*)dst = r0;
        *(float4*)(dst + 4) = r1;
    }
}

// ---------------------------------------------------------------------------
extern "C" void kernel_launch(void* const* d_in, const int* in_sizes, int n_in,
                              void* d_out, int out_size) {
    const float* x    = (const float*)d_in[0];   // [4,4096,128]
    const float* Wfc  = (const float*)d_in[1];   // [128,384]
    const float* bfc  = (const float*)d_in[2];   // [384]
    const float* Wout = (const float*)d_in[3];   // [128,128]
    const float* bo   = (const float*)d_in[4];   // [128]
    const float* sc   = (const float*)d_in[5];   // [1]
    float* out = (float*)d_out;                  // [4,4096,128]

    const int smem1 = (8192 + 128 * 68) * 4;          // 67584 B
    const int smem2 = (8192 * 3 + 64 * 68) * 4;       // 115712 B
    cudaFuncSetAttribute(qkv_kernel, cudaFuncAttributeMaxDynamicSharedMemorySize, smem1);
    cudaFuncSetAttribute(attn_kernel, cudaFuncAttributeMaxDynamicSharedMemorySize, smem2);

    qkv_kernel<<<dim3(256, 6), 256, smem1>>>(x, Wfc, bfc);
    attn_kernel<<<dim3(64, 4), 256, smem2>>>(Wout, bo, sc, out);
}

// round 3
// speedup vs baseline: 1.8035x; 1.8028x over previous
#include <cuda_runtime.h>
#include <math.h>

#define BATCH 4
#define SEQ   4096
#define CDIM  128
#define MTOT  (BATCH*SEQ)   // 16384

// Scratch for Q,K,V projections — __device__ globals per harness rules.
__device__ float g_Q[MTOT*CDIM];
__device__ float g_K[MTOT*CDIM];
__device__ float g_V[MTOT*CDIM];

// XOR swizzle for [rows x 128-float] tiles stored as float4 (32 f4 per row).
__device__ __forceinline__ int sw_idx(int row, int kc) {
    return row * 32 + (kc ^ (row & 31));
}

// ---------------------------------------------------------------------------
// Kernel 1: QKV projection. out[m][c] = sum_k x[m][k]*W_fc[k][c] + b_fc[c]
// Grid: (256 m-tiles, 6 c-tiles of 64). Block: 256 threads, 4x4 micro-tiles.
// ---------------------------------------------------------------------------
__global__ __launch_bounds__(256, 1)
void qkv_kernel(const float* __restrict__ x, const float* __restrict__ Wfc,
                const float* __restrict__ bfc) {
    extern __shared__ float smem[];
    float4* Xs4 = (float4*)smem;               // 64x128 swizzled (2048 f4)
    float4* Ws4 = (float4*)(smem + 8192);      // 128 rows x 68 floats (17 f4 stride)

    const int tid = threadIdx.x;
    const int tx = tid & 15, ty = tid >> 4;
    const int m0 = ty * 4, n0 = tx * 4;
    const int mbase = blockIdx.x * 64;
    const int cbase = blockIdx.y * 64;

    const float4* xg = (const float4*)(x + (size_t)mbase * CDIM);
    #pragma unroll
    for (int i = 0; i < 8; i++) {
        int idx = i * 256 + tid;
        Xs4[sw_idx(idx >> 5, idx & 31)] = xg[idx];
    }
    #pragma unroll
    for (int i = 0; i < 8; i++) {
        int idx = i * 256 + tid;
        int kr = idx >> 4, nq = idx & 15;
        Ws4[kr * 17 + nq] = ((const float4*)(Wfc + kr * 384 + cbase))[nq];
    }
    __syncthreads();

    float acc[4][4];
    #pragma unroll
    for (int i = 0; i < 4; i++)
        #pragma unroll
        for (int j = 0; j < 4; j++) acc[i][j] = 0.f;

    #pragma unroll 4
    for (int k4 = 0; k4 < 32; k4++) {
        float4 b0 = Ws4[(4 * k4 + 0) * 17 + tx];
        float4 b1 = Ws4[(4 * k4 + 1) * 17 + tx];
        float4 b2 = Ws4[(4 * k4 + 2) * 17 + tx];
        float4 b3 = Ws4[(4 * k4 + 3) * 17 + tx];
        #pragma unroll
        for (int i = 0; i < 4; i++) {
            float4 a = Xs4[sw_idx(m0 + i, k4)];
            acc[i][0] += a.x * b0.x + a.y * b1.x + a.z * b2.x + a.w * b3.x;
            acc[i][1] += a.x * b0.y + a.y * b1.y + a.z * b2.y + a.w * b3.y;
            acc[i][2] += a.x * b0.z + a.y * b1.z + a.z * b2.z + a.w * b3.z;
            acc[i][3] += a.x * b0.w + a.y * b1.w + a.z * b2.w + a.w * b3.w;
        }
    }

    float4 bias = *(const float4*)(bfc + cbase + n0);
    int sel = cbase >> 7;
    float* buf = (sel == 0) ? g_Q : (sel == 1) ? g_K : g_V;
    int lc = (cbase & 127) + n0;
    #pragma unroll
    for (int i = 0; i < 4; i++) {
        float4 o;
        o.x = acc[i][0] + bias.x;
        o.y = acc[i][1] + bias.y;
        o.z = acc[i][2] + bias.z;
        o.w = acc[i][3] + bias.w;
        *(float4*)(buf + (size_t)(mbase + m0 + i) * CDIM + lc) = o;
    }
}

// ---------------------------------------------------------------------------
// Kernel 2: flash attention + fused output projection.
// Grid: (32 q-tiles of 128 rows, 4 batches) = 128 CTAs, one wave.
// Block: 256 threads as 16(ty) x 16(tx).
//   QK phase: micro-tile 8 rows (ty*8) x 4 cols (tx + 16j)  -> S[8][4]
//   PV phase: micro-tile 8 rows x 8 cols (tx*8)             -> O[8][8]
// SMEM (floats): Qs[0:16384] Ks[16384:24576] Vs[24576:32768] P[32768:41472]
//   epilogue reuse: O -> Qs region (swizzled), W_out -> Ks+Vs region.
// ---------------------------------------------------------------------------
__global__ __launch_bounds__(256, 1)
void attn_kernel(const float* __restrict__ Wout, const float* __restrict__ bout,
                 const float* __restrict__ scale, float* __restrict__ out) {
    extern __shared__ float smem[];
    float4* Qs4 = (float4*)smem;                 // 4096 f4, swizzled (128x128)
    float4* Ks4 = (float4*)(smem + 16384);       // 2048 f4, swizzled (64x128)
    float4* Vs4 = (float4*)(smem + 24576);       // 2048 f4, linear   (64x128)
    float*  Psm = smem + 32768;                  // 128 x 68 floats (padded)
    float4* Ws4 = (float4*)(smem + 16384);       // reuse K+V: 4096 f4 (64 KB)
    float*  OsmF = smem;                         // reuse Q region for O

    const int tid = threadIdx.x;
    const int tx = tid & 15, ty = tid >> 4;
    const int m0 = ty * 8;
    const int b = blockIdx.y;
    const int qr0 = blockIdx.x * 128;

    const float s0 = scale[0];
    const float sc = 1.0f / (sqrtf((float)CDIM) * s0);

    // Load Q tile (128 x 128)
    const float4* qg = (const float4*)(g_Q + (size_t)(b * SEQ + qr0) * CDIM);
    #pragma unroll
    for (int i = 0; i < 16; i++) {
        int idx = i * 256 + tid;
        Qs4[sw_idx(idx >> 5, idx & 31)] = qg[idx];
    }

    float O[8][8];
    float mrow[8], lrow[8];
    #pragma unroll
    for (int i = 0; i < 8; i++) {
        mrow[i] = -1e30f; lrow[i] = 0.f;
        #pragma unroll
        for (int cc = 0; cc < 8; cc++) O[i][cc] = 0.f;
    }

    for (int jt = 0; jt < SEQ / 64; jt++) {
        __syncthreads();   // prior iter's P/V reads complete
        const int kr0 = jt * 64;
        const float4* kg = (const float4*)(g_K + (size_t)(b * SEQ + kr0) * CDIM);
        const float4* vg = (const float4*)(g_V + (size_t)(b * SEQ + kr0) * CDIM);
        #pragma unroll
        for (int i = 0; i < 8; i++) {
            int idx = i * 256 + tid;
            Ks4[sw_idx(idx >> 5, idx & 31)] = kg[idx];
            Vs4[idx] = vg[idx];
        }
        __syncthreads();

        // S[i][j] = Q[m0+i] . K[tx+16j] over k=128
        float s[8][4];
        #pragma unroll
        for (int i = 0; i < 8; i++)
            #pragma unroll
            for (int j = 0; j < 4; j++) s[i][j] = 0.f;

        #pragma unroll 2
        for (int k4 = 0; k4 < 32; k4++) {
            float4 kf0 = Ks4[sw_idx(tx +  0, k4)];
            float4 kf1 = Ks4[sw_idx(tx + 16, k4)];
            float4 kf2 = Ks4[sw_idx(tx + 32, k4)];
            float4 kf3 = Ks4[sw_idx(tx + 48, k4)];
            #pragma unroll
            for (int i = 0; i < 8; i++) {
                float4 a = Qs4[sw_idx(m0 + i, k4)];   // broadcast
                s[i][0] += a.x * kf0.x + a.y * kf0.y + a.z * kf0.z + a.w * kf0.w;
                s[i][1] += a.x * kf1.x + a.y * kf1.y + a.z * kf1.z + a.w * kf1.w;
                s[i][2] += a.x * kf2.x + a.y * kf2.y + a.z * kf2.z + a.w * kf2.w;
                s[i][3] += a.x * kf3.x + a.y * kf3.y + a.z * kf3.z + a.w * kf3.w;
            }
        }

        // Online softmax: row reductions across the 16 tx lanes of each ty group.
        #pragma unroll
        for (int i = 0; i < 8; i++) {
            s[i][0] *= sc; s[i][1] *= sc; s[i][2] *= sc; s[i][3] *= sc;
            float rm = fmaxf(fmaxf(s[i][0], s[i][1]), fmaxf(s[i][2], s[i][3]));
            rm = fmaxf(rm, __shfl_xor_sync(0xffffffffu, rm, 1));
            rm = fmaxf(rm, __shfl_xor_sync(0xffffffffu, rm, 2));
            rm = fmaxf(rm, __shfl_xor_sync(0xffffffffu, rm, 4));
            rm = fmaxf(rm, __shfl_xor_sync(0xffffffffu, rm, 8));
            float nm = fmaxf(mrow[i], rm);
            float al = __expf(mrow[i] - nm);
            mrow[i] = nm;
            float rs = 0.f;
            #pragma unroll
            for (int j = 0; j < 4; j++) {
                float p = __expf(s[i][j] - nm);
                s[i][j] = p; rs += p;
            }
            rs += __shfl_xor_sync(0xffffffffu, rs, 1);
            rs += __shfl_xor_sync(0xffffffffu, rs, 2);
            rs += __shfl_xor_sync(0xffffffffu, rs, 4);
            rs += __shfl_xor_sync(0xffffffffu, rs, 8);
            lrow[i] = lrow[i] * al + rs;
            #pragma unroll
            for (int cc = 0; cc < 8; cc++) O[i][cc] *= al;
        }

        // Stage P (cols tx+16j per thread)
        #pragma unroll
        for (int i = 0; i < 8; i++) {
            #pragma unroll
            for (int j = 0; j < 4; j++)
                Psm[(m0 + i) * 68 + tx + 16 * j] = s[i][j];
        }
        __syncthreads();

        // O += P @ V   (8 rows x 8 cols per thread, cols tx*8..tx*8+7)
        #pragma unroll 2
        for (int kk = 0; kk < 64; kk++) {
            float4 v0 = Vs4[kk * 32 + 2 * tx];
            float4 v1 = Vs4[kk * 32 + 2 * tx + 1];
            #pragma unroll
            for (int i = 0; i < 8; i++) {
                float p = Psm[(m0 + i) * 68 + kk];   // broadcast
                O[i][0] += p * v0.x; O[i][1] += p * v0.y;
                O[i][2] += p * v0.z; O[i][3] += p * v0.w;
                O[i][4] += p * v1.x; O[i][5] += p * v1.y;
                O[i][6] += p * v1.z; O[i][7] += p * v1.w;
            }
        }
    }
    __syncthreads();

    // Normalize, stash O into Q region (same swizzle), cache W_out in K+V region
    #pragma unroll
    for (int i = 0; i < 8; i++) {
        float inv = 1.0f / lrow[i];
        Qs4[sw_idx(m0 + i, 2 * tx)] =
            make_float4(O[i][0] * inv, O[i][1] * inv, O[i][2] * inv, O[i][3] * inv);
        Qs4[sw_idx(m0 + i, 2 * tx + 1)] =
            make_float4(O[i][4] * inv, O[i][5] * inv, O[i][6] * inv, O[i][7] * inv);
    }
    #pragma unroll
    for (int i = 0; i < 16; i++) {
        int idx = i * 256 + tid;           // 4096 f4 = full 128x128 W_out
        Ws4[idx] = ((const float4*)Wout)[idx];
    }
    __syncthreads();

    // out = O @ W_out + b_out (reuse O registers as accumulators)
    #pragma unroll
    for (int i = 0; i < 8; i++)
        #pragma unroll
        for (int cc = 0; cc < 8; cc++) O[i][cc] = 0.f;

    #pragma unroll 2
    for (int k = 0; k < 128; k++) {
        float4 w0 = Ws4[k * 32 + 2 * tx];
        float4 w1 = Ws4[k * 32 + 2 * tx + 1];
        #pragma unroll
        for (int i = 0; i < 8; i++) {
            float a = OsmF[sw_idx(m0 + i, k >> 2) * 4 + (k & 3)];  // broadcast
            O[i][0] += a * w0.x; O[i][1] += a * w0.y;
            O[i][2] += a * w0.z; O[i][3] += a * w0.w;
            O[i][4] += a * w1.x; O[i][5] += a * w1.y;
            O[i][6] += a * w1.z; O[i][7] += a * w1.w;
        }
    }

    float4 bo0 = ((const float4*)bout)[2 * tx];
    float4 bo1 = ((const float4*)bout)[2 * tx + 1];
    #pragma unroll
    for (int i = 0; i < 8; i++) {
        float4 r0 = make_float4(O[i][0] + bo0.x, O[i][1] + bo0.y,
                                O[i][2] + bo0.z, O[i][3] + bo0.w);
        float4 r1 = make_float4(O[i][4] + bo1.x, O[i][5] + bo1.y,
                                O[i][6] + bo1.z, O[i][7] + bo1.w);
        float* dst = out + (size_t)(b * SEQ + qr0 + m0 + i) * CDIM + tx * 8;
        *(float4*)dst = r0;
        *(float4*)(dst + 4) = r1;
    }
}

// ---------------------------------------------------------------------------
extern "C" void kernel_launch(void* const* d_in, const int* in_sizes, int n_in,
                              void* d_out, int out_size) {
    const float* x    = (const float*)d_in[0];   // [4,4096,128]
    const float* Wfc  = (const float*)d_in[1];   // [128,384]
    const float* bfc  = (const float*)d_in[2];   // [384]
    const float* Wout = (const float*)d_in[3];   // [128,128]
    const float* bo   = (const float*)d_in[4];   // [128]
    const float* sc   = (const float*)d_in[5];   // [1]
    float* out = (float*)d_out;                  // [4,4096,128]

    const int smem1 = (8192 + 128 * 68) * 4;          // 67584 B
    const int smem2 = (16384 + 8192 + 8192 + 128 * 68) * 4;  // 165888 B
    cudaFuncSetAttribute(qkv_kernel, cudaFuncAttributeMaxDynamicSharedMemorySize, smem1);
    cudaFuncSetAttribute(attn_kernel, cudaFuncAttributeMaxDynamicSharedMemorySize, smem2);

    qkv_kernel<<<dim3(256, 6), 256, smem1>>>(x, Wfc, bfc);
    attn_kernel<<<dim3(32, 4), 256, smem2>>>(Wout, bo, sc, out);
}

// round 6
// speedup vs baseline: 5.6771x; 3.1478x over previous
#include <cuda_runtime.h>
#include <cuda_bf16.h>
#include <math.h>
#include <stdint.h>

#define BATCH 4
#define SEQ   4096
#define CDIM  128
#define MTOT  (BATCH*SEQ)
#define KVT   64
#define NTILES (SEQ/KVT)

// bf16 hi/lo split operands (scale folded into Q). V stored TRANSPOSED per batch: [b][c][n].
__device__ __nv_bfloat16 g_Qh[MTOT*CDIM], g_Ql[MTOT*CDIM];
__device__ __nv_bfloat16 g_Kh[MTOT*CDIM], g_Kl[MTOT*CDIM];
__device__ __nv_bfloat16 g_Vth[MTOT*CDIM], g_Vtl[MTOT*CDIM];

// ---------------- warp-MMA helpers (baseline PTX, sm_80+) ----------------
__device__ __forceinline__ uint32_t smem_u32(const void* p) {
    uint32_t a;
    asm("{ .reg .u64 t; cvta.to.shared.u64 t, %1; cvt.u32.u64 %0, t; }" : "=r"(a) : "l"(p));
    return a;
}
#define LDSM_X4(r0, r1, r2, r3, addr) \
    asm volatile("ldmatrix.sync.aligned.m8n8.x4.shared.b16 {%0,%1,%2,%3}, [%4];" \
        : "=r"(r0), "=r"(r1), "=r"(r2), "=r"(r3) : "r"(addr))

__device__ __forceinline__ void mma_bf16(float c[4], const uint32_t a[4],
                                         uint32_t b0, uint32_t b1) {
    asm volatile("mma.sync.aligned.m16n8k16.row.col.f32.bf16.bf16.f32 "
        "{%0,%1,%2,%3}, {%4,%5,%6,%7}, {%8,%9}, {%0,%1,%2,%3};"
        : "+f"(c[0]), "+f"(c[1]), "+f"(c[2]), "+f"(c[3])
        : "r"(a[0]), "r"(a[1]), "r"(a[2]), "r"(a[3]), "r"(b0), "r"(b1));
}

// bf16 split helpers
__device__ __forceinline__ uint32_t pack_hi2(float a, float b, float& ra, float& rb) {
    __nv_bfloat162 h = __floats2bfloat162_rn(a, b);
    ra = a - __bfloat162float(h.x);
    rb = b - __bfloat162float(h.y);
    return *(uint32_t*)&h;
}
__device__ __forceinline__ uint32_t pack2(float a, float b) {
    __nv_bfloat162 h = __floats2bfloat162_rn(a, b);
    return *(uint32_t*)&h;
}

// ---------------------------------------------------------------------------
// Kernel 1: QKV projection -> bf16 hi/lo splits. Q scaled by 1/(sqrt(C)*scale).
// V written transposed per batch: g_Vt[b][c][n]. (fp32 compute, exact)
// ---------------------------------------------------------------------------
__global__ __launch_bounds__(256, 1)
void qkv_kernel(const float* __restrict__ x, const float* __restrict__ Wfc,
                const float* __restrict__ bfc, const float* __restrict__ scale) {
    extern __shared__ float smem[];
    float4* Xs4 = (float4*)smem;               // 64x128 swizzled (2048 f4)
    float4* Ws4 = (float4*)(smem + 8192);      // 128 x 17 f4 (stride-68 floats)

    const int tid = threadIdx.x;
    const int tx = tid & 15, ty = tid >> 4;
    const int m0 = ty * 4, n0 = tx * 4;
    const int mbase = blockIdx.x * 64;
    const int cbase = blockIdx.y * 64;

    const float4* xg = (const float4*)(x + (size_t)mbase * CDIM);
    #pragma unroll
    for (int i = 0; i < 8; i++) {
        int idx = i * 256 + tid;
        int r = idx >> 5, kc = idx & 31;
        Xs4[r * 32 + (kc ^ (r & 31))] = xg[idx];
    }
    #pragma unroll
    for (int i = 0; i < 8; i++) {
        int idx = i * 256 + tid;
        int kr = idx >> 4, nq = idx & 15;
        Ws4[kr * 17 + nq] = ((const float4*)(Wfc + kr * 384 + cbase))[nq];
    }
    __syncthreads();

    float acc[4][4];
    #pragma unroll
    for (int i = 0; i < 4; i++)
        #pragma unroll
        for (int j = 0; j < 4; j++) acc[i][j] = 0.f;

    #pragma unroll 4
    for (int k4 = 0; k4 < 32; k4++) {
        float4 b0 = Ws4[(4 * k4 + 0) * 17 + tx];
        float4 b1 = Ws4[(4 * k4 + 1) * 17 + tx];
        float4 b2 = Ws4[(4 * k4 + 2) * 17 + tx];
        float4 b3 = Ws4[(4 * k4 + 3) * 17 + tx];
        #pragma unroll
        for (int i = 0; i < 4; i++) {
            float4 a = Xs4[(m0 + i) * 32 + (k4 ^ ((m0 + i) & 31))];
            acc[i][0] += a.x * b0.x + a.y * b1.x + a.z * b2.x + a.w * b3.x;
            acc[i][1] += a.x * b0.y + a.y * b1.y + a.z * b2.y + a.w * b3.y;
            acc[i][2] += a.x * b0.z + a.y * b1.z + a.z * b2.z + a.w * b3.z;
            acc[i][3] += a.x * b0.w + a.y * b1.w + a.z * b2.w + a.w * b3.w;
        }
    }

    float4 bias = *(const float4*)(bfc + cbase + n0);
    const int sel = blockIdx.y >> 1;            // 0=Q, 1=K, 2=V

    if (sel < 2) {
        float mul = 1.0f;
        if (sel == 0) mul = 1.0f / (sqrtf((float)CDIM) * scale[0]);
        __nv_bfloat16* bh = sel ? g_Kh : g_Qh;
        __nv_bfloat16* bl = sel ? g_Kl : g_Ql;
        const int lc = ((blockIdx.y & 1) << 6) + n0;
        #pragma unroll
        for (int i = 0; i < 4; i++) {
            float v0 = (acc[i][0] + bias.x) * mul;
            float v1 = (acc[i][1] + bias.y) * mul;
            float v2 = (acc[i][2] + bias.z) * mul;
            float v3 = (acc[i][3] + bias.w) * mul;
            float r0, r1, r2, r3;
            uint32_t h01 = pack_hi2(v0, v1, r0, r1);
            uint32_t h23 = pack_hi2(v2, v3, r2, r3);
            uint32_t l01 = pack2(r0, r1);
            uint32_t l23 = pack2(r2, r3);
            size_t off = (size_t)(mbase + m0 + i) * CDIM + lc;
            *(uint2*)(bh + off) = make_uint2(h01, h23);
            *(uint2*)(bl + off) = make_uint2(l01, l23);
        }
    } else {
        // transpose via SMEM, then coalesced bf16-split stores to g_Vt[b][c][n]
        __syncthreads();
        float* T = smem;                        // 64 x 65
        #pragma unroll
        for (int i = 0; i < 4; i++) {
            T[(m0 + i) * 65 + n0 + 0] = acc[i][0] + bias.x;
            T[(m0 + i) * 65 + n0 + 1] = acc[i][1] + bias.y;
            T[(m0 + i) * 65 + n0 + 2] = acc[i][2] + bias.z;
            T[(m0 + i) * 65 + n0 + 3] = acc[i][3] + bias.w;
        }
        __syncthreads();
        const int c_local = tid & 63, seg = tid >> 6;
        const int cg = ((blockIdx.y & 1) << 6) + c_local;
        const int bb = mbase >> 12;
        size_t basea = ((size_t)(bb * CDIM + cg)) * SEQ + (mbase & 4095) + seg * 16;
        uint32_t hw[8], lw[8];
        #pragma unroll
        for (int u = 0; u < 8; u++) {
            float v0 = T[(seg * 16 + 2 * u) * 65 + c_local];
            float v1 = T[(seg * 16 + 2 * u + 1) * 65 + c_local];
            float r0, r1;
            hw[u] = pack_hi2(v0, v1, r0, r1);
            lw[u] = pack2(r0, r1);
        }
        *(uint4*)(g_Vth + basea)     = make_uint4(hw[0], hw[1], hw[2], hw[3]);
        *(uint4*)(g_Vth + basea + 8) = make_uint4(hw[4], hw[5], hw[6], hw[7]);
        *(uint4*)(g_Vtl + basea)     = make_uint4(lw[0], lw[1], lw[2], lw[3]);
        *(uint4*)(g_Vtl + basea + 8) = make_uint4(lw[4], lw[5], lw[6], lw[7]);
    }
}

// ---------------------------------------------------------------------------
// Kernel 2: warp-MMA (HMMA) flash attention + fused output projection.
// Grid (32, 4) = 128 CTAs (one wave). Block 256 threads = 8 warps.
// Warp w owns Q rows [w*16, w*16+16). Q in registers; S->P->PV in registers
// (C-fragment of S == A-fragment for PV). 3-chain bf16 splits throughout.
// SMEM: Kh[64x136]272B-stride, Kl, Vth[128x72]144B-stride, Vtl. 70KB.
// Epilogue: W_out^T hi/lo reuse SMEM, same register GEMM, + bias, store.
// ---------------------------------------------------------------------------
#define QSTR 136   // bf16 stride (272B) for Q/K/W tiles: conflict-free ldmatrix
#define VSTR 72    // bf16 stride (144B) for Vt tiles
#define OFF_KH 0
#define OFF_KL 17408
#define OFF_VH 34816
#define OFF_VL 53248
#define SM_TOT 71680

__global__ __launch_bounds__(256, 1)
void attn_kernel(const float* __restrict__ Wout, const float* __restrict__ bout,
                 float* __restrict__ out) {
    extern __shared__ char smem8[];
    const uint32_t sb = smem_u32(smem8);
    const int tid = threadIdx.x, lane = tid & 31, w = tid >> 5;
    const int b = blockIdx.y;
    const int qr0 = blockIdx.x * 128;

    // B-fragment lane addressing (ldmatrix.x4 over a 16-row n-pair)
    const int bn  = (lane & 7) | ((lane & 16) >> 1);   // n row within 16
    const int bk8 = (lane & 8);                         // +8 k offset
    // A-fragment lane addressing
    const int ar  = lane & 15;
    const int ac8 = (lane >> 4) << 3;

    // ---- stage Qh then Ql through SMEM (reuses K region), load A fragments ----
    // Q tile = 128 rows x 128 cols bf16 = 2048 uint4 -> 8 iterations of 256 threads.
    uint32_t qh[8][4], ql[8][4];
    {
        __nv_bfloat16* Qs = (__nv_bfloat16*)smem8;
        #pragma unroll
        for (int i = 0; i < 8; i++) {
            int idx = i * 256 + tid;
            int r = idx >> 4, c = (idx & 15) << 3;
            *(uint4*)(Qs + r * QSTR + c) =
                *(const uint4*)(g_Qh + (size_t)(b * SEQ + qr0 + r) * CDIM + c);
        }
        __syncthreads();
        #pragma unroll
        for (int kk = 0; kk < 8; kk++) {
            uint32_t a = sb + ((w * 16 + ar) * QSTR + kk * 16 + ac8) * 2;
            LDSM_X4(qh[kk][0], qh[kk][1], qh[kk][2], qh[kk][3], a);
        }
        __syncthreads();
        #pragma unroll
        for (int i = 0; i < 8; i++) {
            int idx = i * 256 + tid;
            int r = idx >> 4, c = (idx & 15) << 3;
            *(uint4*)(Qs + r * QSTR + c) =
                *(const uint4*)(g_Ql + (size_t)(b * SEQ + qr0 + r) * CDIM + c);
        }
        __syncthreads();
        #pragma unroll
        for (int kk = 0; kk < 8; kk++) {
            uint32_t a = sb + ((w * 16 + ar) * QSTR + kk * 16 + ac8) * 2;
            LDSM_X4(ql[kk][0], ql[kk][1], ql[kk][2], ql[kk][3], a);
        }
    }

    float co[16][4];
    #pragma unroll
    for (int i = 0; i < 16; i++)
        #pragma unroll
        for (int j = 0; j < 4; j++) co[i][j] = 0.f;
    float l0 = 0.f, l1 = 0.f;

    for (int t = 0; t < NTILES; t++) {
        const int kr0 = t * KVT;
        __syncthreads();   // previous tile's SMEM reads complete
        // K tiles: 64 rows x 128 bf16 (hi & lo) = 1024 uint4 each
        #pragma unroll
        for (int i = 0; i < 4; i++) {
            int idx = i * 256 + tid;
            int r = idx >> 4, c = (idx & 15) << 3;
            size_t g = (size_t)(b * SEQ + kr0 + r) * CDIM + c;
            *(uint4*)(smem8 + OFF_KH + r * (QSTR * 2) + c * 2) = *(const uint4*)(g_Kh + g);
            *(uint4*)(smem8 + OFF_KL + r * (QSTR * 2) + c * 2) = *(const uint4*)(g_Kl + g);
        }
        // Vt tiles: 128 rows (c) x 64 bf16 (kv) = 1024 uint4 each
        #pragma unroll
        for (int i = 0; i < 4; i++) {
            int idx = i * 256 + tid;
            int r = idx >> 3, j8 = (idx & 7) << 3;
            size_t g = (size_t)(b * CDIM + r) * SEQ + kr0 + j8;
            *(uint4*)(smem8 + OFF_VH + r * (VSTR * 2) + j8 * 2) = *(const uint4*)(g_Vth + g);
            *(uint4*)(smem8 + OFF_VL + r * (VSTR * 2) + j8 * 2) = *(const uint4*)(g_Vtl + g);
        }
        __syncthreads();

        // ---- S = Q.K^T (3 chains) ----
        float cs[8][4];
        #pragma unroll
        for (int i = 0; i < 8; i++)
            #pragma unroll
            for (int j = 0; j < 4; j++) cs[i][j] = 0.f;

        #pragma unroll
        for (int kk = 0; kk < 8; kk++) {
            #pragma unroll
            for (int nbp = 0; nbp < 4; nbp++) {
                uint32_t off = ((nbp * 16 + bn) * (QSTR * 2)) + (kk * 16 + bk8) * 2;
                uint32_t h0, h1, h2, h3, l0r, l1r, l2r, l3r;
                LDSM_X4(h0, h1, h2, h3, sb + OFF_KH + off);
                LDSM_X4(l0r, l1r, l2r, l3r, sb + OFF_KL + off);
                mma_bf16(cs[2 * nbp],     qh[kk], h0, h1);
                mma_bf16(cs[2 * nbp + 1], qh[kk], h2, h3);
                mma_bf16(cs[2 * nbp],     qh[kk], l0r, l1r);
                mma_bf16(cs[2 * nbp + 1], qh[kk], l2r, l3r);
                mma_bf16(cs[2 * nbp],     ql[kk], h0, h1);
                mma_bf16(cs[2 * nbp + 1], ql[kk], h2, h3);
            }
        }

        // ---- P = exp(S); accumulate l; pack into A fragments (hi/lo) ----
        uint32_t pah[4][4], pal[4][4];
        #pragma unroll
        for (int nb = 0; nb < 8; nb++) {
            cs[nb][0] = __expf(cs[nb][0]);
            cs[nb][1] = __expf(cs[nb][1]);
            cs[nb][2] = __expf(cs[nb][2]);
            cs[nb][3] = __expf(cs[nb][3]);
            l0 += cs[nb][0] + cs[nb][1];
            l1 += cs[nb][2] + cs[nb][3];
        }
        #pragma unroll
        for (int j = 0; j < 4; j++) {
            float r0, r1;
            pah[j][0] = pack_hi2(cs[2*j][0],   cs[2*j][1],   r0, r1); pal[j][0] = pack2(r0, r1);
            pah[j][1] = pack_hi2(cs[2*j][2],   cs[2*j][3],   r0, r1); pal[j][1] = pack2(r0, r1);
            pah[j][2] = pack_hi2(cs[2*j+1][0], cs[2*j+1][1], r0, r1); pal[j][2] = pack2(r0, r1);
            pah[j][3] = pack_hi2(cs[2*j+1][2], cs[2*j+1][3], r0, r1); pal[j][3] = pack2(r0, r1);
        }

        // ---- O += P.V (3 chains) ----
        #pragma unroll
        for (int kk = 0; kk < 4; kk++) {
            #pragma unroll
            for (int nbp = 0; nbp < 8; nbp++) {
                uint32_t off = ((nbp * 16 + bn) * (VSTR * 2)) + (kk * 16 + bk8) * 2;
                uint32_t h0, h1, h2, h3, l0r, l1r, l2r, l3r;
                LDSM_X4(h0, h1, h2, h3, sb + OFF_VH + off);
                LDSM_X4(l0r, l1r, l2r, l3r, sb + OFF_VL + off);
                mma_bf16(co[2 * nbp],     pah[kk], h0, h1);
                mma_bf16(co[2 * nbp + 1], pah[kk], h2, h3);
                mma_bf16(co[2 * nbp],     pah[kk], l0r, l1r);
                mma_bf16(co[2 * nbp + 1], pah[kk], l2r, l3r);
                mma_bf16(co[2 * nbp],     pal[kk], h0, h1);
                mma_bf16(co[2 * nbp + 1], pal[kk], h2, h3);
            }
        }
    }

    // ---- finalize l (4 lanes share each row), normalize O ----
    l0 += __shfl_xor_sync(0xffffffffu, l0, 1);
    l0 += __shfl_xor_sync(0xffffffffu, l0, 2);
    l1 += __shfl_xor_sync(0xffffffffu, l1, 1);
    l1 += __shfl_xor_sync(0xffffffffu, l1, 2);
    const float inv0 = 1.0f / l0, inv1 = 1.0f / l1;
    #pragma unroll
    for (int nb = 0; nb < 16; nb++) {
        co[nb][0] *= inv0; co[nb][1] *= inv0;
        co[nb][2] *= inv1; co[nb][3] *= inv1;
    }

    // ---- W_out^T hi/lo -> SMEM (reuse) ----
    __syncthreads();
    {
        __nv_bfloat16* Wh = (__nv_bfloat16*)smem8;             // 128 x QSTR
        __nv_bfloat16* Wl = (__nv_bfloat16*)(smem8 + OFF_VH);  // 128 x QSTR
        for (int idx = tid; idx < CDIM * CDIM; idx += 256) {
            int cin = idx >> 7, cout = idx & 127;
            float wv = Wout[idx];
            __nv_bfloat16 hh = __float2bfloat16(wv);
            __nv_bfloat16 ll = __float2bfloat16(wv - __bfloat162float(hh));
            Wh[cout * QSTR + cin] = hh;
            Wl[cout * QSTR + cin] = ll;
        }
    }

    // ---- O -> A fragments (hi/lo) ----
    uint32_t oah[8][4], oal[8][4];
    #pragma unroll
    for (int j = 0; j < 8; j++) {
        float r0, r1;
        oah[j][0] = pack_hi2(co[2*j][0],   co[2*j][1],   r0, r1); oal[j][0] = pack2(r0, r1);
        oah[j][1] = pack_hi2(co[2*j][2],   co[2*j][3],   r0, r1); oal[j][1] = pack2(r0, r1);
        oah[j][2] = pack_hi2(co[2*j+1][0], co[2*j+1][1], r0, r1); oal[j][2] = pack2(r0, r1);
        oah[j][3] = pack_hi2(co[2*j+1][2], co[2*j+1][3], r0, r1); oal[j][3] = pack2(r0, r1);
    }
    __syncthreads();

    // ---- D = O @ W_out (3 chains), accumulate into co (reused) ----
    #pragma unroll
    for (int i = 0; i < 16; i++)
        #pragma unroll
        for (int j = 0; j < 4; j++) co[i][j] = 0.f;

    #pragma unroll
    for (int kk = 0; kk < 8; kk++) {
        #pragma unroll
        for (int nbp = 0; nbp < 8; nbp++) {
            uint32_t off = ((nbp * 16 + bn) * (QSTR * 2)) + (kk * 16 + bk8) * 2;
            uint32_t h0, h1, h2, h3, l0r, l1r, l2r, l3r;
            LDSM_X4(h0, h1, h2, h3, sb + off);
            LDSM_X4(l0r, l1r, l2r, l3r, sb + OFF_VH + off);
            mma_bf16(co[2 * nbp],     oah[kk], h0, h1);
            mma_bf16(co[2 * nbp + 1], oah[kk], h2, h3);
            mma_bf16(co[2 * nbp],     oah[kk], l0r, l1r);
            mma_bf16(co[2 * nbp + 1], oah[kk], l2r, l3r);
            mma_bf16(co[2 * nbp],     oal[kk], h0, h1);
            mma_bf16(co[2 * nbp + 1], oal[kk], h2, h3);
        }
    }

    // ---- + bias, store ----
    {
        const int r0g = qr0 + w * 16 + (lane >> 2);
        const int cb = (lane & 3) * 2;
        float* base0 = out + (size_t)(b * SEQ + r0g) * CDIM;
        float* base1 = base0 + 8 * CDIM;
        #pragma unroll
        for (int nb = 0; nb < 16; nb++) {
            int col = nb * 8 + cb;
            float bx = bout[col], by = bout[col + 1];
            float2 v0 = make_float2(co[nb][0] + bx, co[nb][1] + by);
            float2 v1 = make_float2(co[nb][2] + bx, co[nb][3] + by);
            *(float2*)(base0 + col) = v0;
            *(float2*)(base1 + col) = v1;
        }
    }
}

// ---------------------------------------------------------------------------
extern "C" void kernel_launch(void* const* d_in, const int* in_sizes, int n_in,
                              void* d_out, int out_size) {
    const float* x    = (const float*)d_in[0];
    const float* Wfc  = (const float*)d_in[1];
    const float* bfc  = (const float*)d_in[2];
    const float* Wout = (const float*)d_in[3];
    const float* bo   = (const float*)d_in[4];
    const float* sc   = (const float*)d_in[5];
    float* out = (float*)d_out;

    const int smem1 = (8192 + 128 * 68) * 4;   // 67584 B
    cudaFuncSetAttribute(qkv_kernel, cudaFuncAttributeMaxDynamicSharedMemorySize, smem1);
    cudaFuncSetAttribute(attn_kernel, cudaFuncAttributeMaxDynamicSharedMemorySize, SM_TOT);

    qkv_kernel<<<dim3(256, 6), 256, smem1>>>(x, Wfc, bfc, sc);
    attn_kernel<<<dim3(32, 4), 256, SM_TOT>>>(Wout, bo, out);
}